// round 11
// baseline (speedup 1.0000x reference)
#include <cuda_runtime.h>
#include <math.h>

#define Bn 64
#define Tn 400
#define Hn 256
#define En 128
#define Vn 50000
#define Xn 500

#define OFF_FINAL 0
#define OFF_HS   (Bn*(Vn+Xn))
#define OFF_CS   (OFF_HS + Bn*Hn)
#define OFF_CT   (OFF_CS + Bn*Hn)
#define OFF_ATTN (OFF_CT + Bn*2*Hn)
#define OFF_PGEN (OFF_ATTN + Bn*Tn)
#define OFF_COV  (OFF_PGEN + Bn)

#define NBF 128   // front grid: 1024thr, ~32KB smem -> 1 CTA/SM, 128 <= 148 SMs: resident
#define NBB 148   // back grid: <= SM count -> resident even at 1 CTA/SM (deadlock-proof)
#define NTILES 196  // ceil(50000/256)

__device__ float g_x[Bn*En];
__device__ float g_dec[Bn*2*Hn];
__device__ float g_escore[Bn*Tn];
__device__ float g_outhid[Bn*Hn];
__device__ float g_elog[Bn*Vn];
__device__ float g_rowsum[Bn];

__device__ int g_cnt1 = 0; __device__ volatile int g_sense1 = 0;
__device__ int g_cnt2 = 0; __device__ volatile int g_sense2 = 0;

__device__ __forceinline__ void grid_bar(int* cnt, volatile int* sense, int nb){
    __syncthreads();
    if (threadIdx.x == 0){
        __threadfence();
        int s = *sense;
        if (atomicAdd(cnt, 1) == nb - 1){
            *cnt = 0;
            __threadfence();
            *sense = 1 - s;          // release
        } else {
            while (*sense == s) __nanosleep(64);
        }
        __threadfence();
    }
    __syncthreads();
}

__device__ __forceinline__ float warp_sum(float v){
    #pragma unroll
    for (int o = 16; o > 0; o >>= 1) v += __shfl_xor_sync(0xffffffffu, v, o);
    return v;
}
__device__ __forceinline__ float sigmoidf_(float x){ return 1.0f / (1.0f + expf(-x)); }
__device__ __forceinline__ float tanh_fast(float x){
    float r; asm("tanh.approx.f32 %0, %1;" : "=f"(r) : "f"(x)); return r;
}
__device__ __forceinline__ unsigned long long pack2(float x, float y){
    unsigned long long r; asm("mov.b64 %0, {%1,%2};" : "=l"(r) : "f"(x), "f"(y)); return r;
}
__device__ __forceinline__ void unpack2(unsigned long long a, float &x, float &y){
    asm("mov.b64 {%0,%1}, %2;" : "=f"(x), "=f"(y) : "l"(a));
}
__device__ __forceinline__ unsigned long long fma2_(unsigned long long a, unsigned long long b, unsigned long long c){
    unsigned long long d; asm("fma.rn.f32x2 %0, %1, %2, %3;" : "=l"(d) : "l"(a), "l"(b), "l"(c)); return d;
}

// ================= FRONT: pre -> scores -> attn+ct -> mid  (persistent) =================
__global__ void __launch_bounds__(1024) k_front(
        const int* __restrict__ y_t_1, const float* __restrict__ c_t_1,
        const float* __restrict__ embedding,
        const float* __restrict__ Wxc, const float* __restrict__ bxc,
        const float* __restrict__ h0, const float* __restrict__ c0,
        const float* __restrict__ W_ih, const float* __restrict__ W_hh,
        const float* __restrict__ b_ih, const float* __restrict__ b_hh,
        const float* __restrict__ Wdp, const float* __restrict__ bdp,
        const float* __restrict__ Wv, const float* __restrict__ mask,
        const float* __restrict__ ef, const float* __restrict__ eo,
        const float* __restrict__ stmt,
        const float* __restrict__ Wo1, const float* __restrict__ bo1,
        const float* __restrict__ Wpg, const float* __restrict__ bpg,
        const float* __restrict__ coverage, float* __restrict__ out){
    int tid = threadIdx.x, lane = tid & 31, wid = tid >> 5;
    int blk = blockIdx.x;
    __shared__ float s_ct1[2][512], s_emb[2][128], s_x[2][128], s_h0[2][256];
    __shared__ float s_gates[2][1024], s_hs[2][256], s_cs[2][256];
    __shared__ float dec_s[512], wv_s[512];
    __shared__ float red[1024];
    __shared__ float attn_s[50];
    __shared__ float s_ct[2][512];

    // ---------- phase A: housekeeping + pre (blocks 0..31, 2 batches each) ----------
    { int i4 = blk*1024 + tid;
      if (i4 < (Bn*Tn)/4) ((float4*)(out + OFF_COV))[i4] = ((const float4*)coverage)[i4]; }
    if (blk == 0 && tid < Bn) g_rowsum[tid] = 0.0f;
    if (blk < 32){
        int b0 = blk * 2;
        out[OFF_CT + blk*1024 + tid] = 0.0f;
        {   int y0 = y_t_1[b0], y1 = y_t_1[b0+1];
            if (tid < 512){
                s_ct1[0][tid] = c_t_1[b0*512 + tid];
                s_ct1[1][tid] = c_t_1[(b0+1)*512 + tid];
            } else if (tid < 640){
                s_emb[0][tid-512] = embedding[(size_t)y0*En + (tid-512)];
            } else if (tid < 768){
                s_emb[1][tid-640] = embedding[(size_t)y1*En + (tid-640)];
            } else {
                int i = tid - 768;
                s_h0[0][i] = h0[b0*Hn + i];
                s_h0[1][i] = h0[(b0+1)*Hn + i];
            }
        }
        __syncthreads();
        // x
        for (int j = wid; j < 128; j += 32){
            const float* wr = Wxc + j * 640;
            float a0 = 0.f, a1 = 0.f;
            #pragma unroll
            for (int it = 0; it < 16; it++){
                int k = lane + it*32; float wv = wr[k];
                a0 += s_ct1[0][k] * wv; a1 += s_ct1[1][k] * wv;
            }
            #pragma unroll
            for (int it = 0; it < 4; it++){
                int k = lane + it*32; float wv = wr[512 + k];
                a0 += s_emb[0][k] * wv; a1 += s_emb[1][k] * wv;
            }
            a0 = warp_sum(a0); a1 = warp_sum(a1);
            if (lane == 0){
                float bv = bxc[j];
                s_x[0][j] = a0 + bv; s_x[1][j] = a1 + bv;
                g_x[b0*En + j] = a0 + bv; g_x[(b0+1)*En + j] = a1 + bv;
            }
        }
        __syncthreads();
        // gates
        for (int j = wid; j < 1024; j += 32){
            const float* w1 = W_ih + j * En;
            const float* w2 = W_hh + j * Hn;
            float a0 = 0.f, a1 = 0.f;
            #pragma unroll
            for (int it = 0; it < 4; it++){
                int k = lane + it*32; float wv = w1[k];
                a0 += s_x[0][k] * wv; a1 += s_x[1][k] * wv;
            }
            #pragma unroll
            for (int it = 0; it < 8; it++){
                int k = lane + it*32; float wv = w2[k];
                a0 += s_h0[0][k] * wv; a1 += s_h0[1][k] * wv;
            }
            a0 = warp_sum(a0); a1 = warp_sum(a1);
            if (lane == 0){
                float bv = b_ih[j] + b_hh[j];
                s_gates[0][j] = a0 + bv; s_gates[1][j] = a1 + bv;
            }
        }
        __syncthreads();
        // lstm
        if (tid < 512){
            int bb = tid >> 8, h = tid & 255;
            int b = b0 + bb;
            float ig = sigmoidf_(s_gates[bb][h]);
            float fg = sigmoidf_(s_gates[bb][Hn + h]);
            float gg = tanhf(s_gates[bb][2*Hn + h]);
            float og = sigmoidf_(s_gates[bb][3*Hn + h]);
            float cs = fg * c0[b*Hn + h] + ig * gg;
            float hs = og * tanhf(cs);
            s_hs[bb][h] = hs; s_cs[bb][h] = cs;
            out[OFF_HS + b*Hn + h] = hs;
            out[OFF_CS + b*Hn + h] = cs;
        }
        __syncthreads();
        // dec
        for (int j = wid; j < 512; j += 32){
            const float* wr = Wdp + j * 512;
            float a0 = 0.f, a1 = 0.f;
            #pragma unroll
            for (int it = 0; it < 8; it++){
                int k = lane + it*32; float wv = wr[k];
                a0 += s_hs[0][k] * wv; a1 += s_hs[1][k] * wv;
            }
            #pragma unroll
            for (int it = 0; it < 8; it++){
                int k = lane + it*32; float wv = wr[256 + k];
                a0 += s_cs[0][k] * wv; a1 += s_cs[1][k] * wv;
            }
            a0 = warp_sum(a0); a1 = warp_sum(a1);
            if (lane == 0){
                float bv = bdp[j];
                g_dec[b0*512 + j] = a0 + bv;
                g_dec[(b0+1)*512 + j] = a1 + bv;
            }
        }
    }
    grid_bar(&g_cnt1, &g_sense1, NBF);

    // ---------- phase B: scores (all 128 blocks; block = (b, half-T)) ----------
    {
        int b = blk >> 1, half = blk & 1;
        if (tid < 512){ dec_s[tid] = g_dec[b*512 + tid]; wv_s[tid] = Wv[tid]; }
        __syncthreads();
        for (int i = wid; i < 200; i += 32){
            int t = half*200 + i;
            const float4* efr = (const float4*)(ef + ((size_t)b * Tn + t) * 512);
            float acc = 0.0f;
            #pragma unroll
            for (int it = 0; it < 4; it++){
                int n4 = lane + it*32;
                float4 e4 = efr[n4];
                int n = n4 * 4;
                acc += wv_s[n+0] * tanh_fast(e4.x + dec_s[n+0]);
                acc += wv_s[n+1] * tanh_fast(e4.y + dec_s[n+1]);
                acc += wv_s[n+2] * tanh_fast(e4.z + dec_s[n+2]);
                acc += wv_s[n+3] * tanh_fast(e4.w + dec_s[n+3]);
            }
            acc = warp_sum(acc);
            if (lane == 0) g_escore[b*Tn + t] = expf(acc) * mask[b*Tn + t];
        }
    }
    grid_bar(&g_cnt1, &g_sense1, NBF);

    // ---------- phase C: attn + c_t partials (4 units/block, unit=(b,chunk50)) ----------
    for (int u = 0; u < 4; u++){
        int unit = blk*4 + u;
        int b = unit >> 3, chunk = unit & 7;
        float e = (tid < Tn) ? g_escore[b*Tn + tid] : 0.0f;
        red[tid] = e; __syncthreads();
        #pragma unroll
        for (int k = 512; k > 0; k >>= 1){ if (tid < k) red[tid] += red[tid+k]; __syncthreads(); }
        float S = red[0]; __syncthreads();
        if (tid < 50){
            int t = chunk*50 + tid;
            float a = g_escore[b*Tn + t] / S + stmt[b*Tn + t] * mask[b*Tn + t];
            attn_s[tid] = a;
            out[OFF_ATTN + b*Tn + t] = a;
        }
        __syncthreads();
        {
            int n = tid & 511, th = tid >> 9;
            float acc = 0.0f;
            const float* eor = eo + ((size_t)b*Tn + chunk*50 + th*25) * 512 + n;
            #pragma unroll 5
            for (int tt = 0; tt < 25; tt++)
                acc += attn_s[th*25 + tt] * eor[(size_t)tt * 512];
            red[tid] = acc;
        }
        __syncthreads();
        if (tid < 512) atomicAdd(&out[OFF_CT + b*512 + tid], red[tid] + red[tid+512]);
        __syncthreads();
    }
    grid_bar(&g_cnt1, &g_sense1, NBF);

    // ---------- phase D: outhid + p_gen (blocks 0..31; s_hs/s_cs/s_x persist) ----------
    if (blk < 32){
        int b0 = blk * 2;
        if (tid < 512){
            s_ct[0][tid] = out[OFF_CT + b0*512 + tid];
            s_ct[1][tid] = out[OFF_CT + (b0+1)*512 + tid];
        }
        __syncthreads();
        for (int j = wid; j < 256; j += 32){
            const float* wr = Wo1 + j * 768;
            float a0 = 0.f, a1 = 0.f;
            #pragma unroll
            for (int it = 0; it < 8; it++){
                int k = lane + it*32; float wv = wr[k];
                a0 += s_hs[0][k] * wv; a1 += s_hs[1][k] * wv;
            }
            #pragma unroll
            for (int it = 0; it < 16; it++){
                int k = lane + it*32; float wv = wr[256 + k];
                a0 += s_ct[0][k] * wv; a1 += s_ct[1][k] * wv;
            }
            a0 = warp_sum(a0); a1 = warp_sum(a1);
            if (lane == 0){
                float bv = bo1[j];
                g_outhid[b0*Hn + j] = a0 + bv;
                g_outhid[(b0+1)*Hn + j] = a1 + bv;
            }
        }
        if (wid < 2){
            int bb = wid;
            float acc = 0.0f;
            for (int k = lane; k < 1152; k += 32){
                float v;
                if (k < 512)       v = s_ct[bb][k];
                else if (k < 768)  v = s_hs[bb][k - 512];
                else if (k < 1024) v = s_cs[bb][k - 768];
                else               v = s_x[bb][k - 1024];
                acc += v * Wpg[k];
            }
            acc = warp_sum(acc);
            if (lane == 0) out[OFF_PGEN + b0 + bb] = sigmoidf_(acc + bpg[0]);
        }
    }
}

// ================= BACK: logits -> final -> scatter  (persistent, 148 blocks) =================
__global__ void __launch_bounds__(256) k_back(const float* __restrict__ W,
        const float* __restrict__ bias, const float* __restrict__ extraz,
        const int* __restrict__ ebev, float* __restrict__ out){
    __shared__ unsigned long long As2[32][65];
    __shared__ float Bs[32][264];
    int tid = threadIdx.x;

    // ---------- phase E: logits tiles (grid-stride over 196 tiles) ----------
    for (int tile = blockIdx.x; tile < NTILES; tile += NBB){
        int vbase = tile * 256;
        int tx = tid & 31, ty = tid >> 5;
        int m0 = ty * 8, n0 = tx * 8;
        unsigned long long acc[8][4];
        #pragma unroll
        for (int i = 0; i < 8; i++){
            #pragma unroll
            for (int q = 0; q < 4; q++) acc[i][q] = 0ull;
        }
        for (int kc = 0; kc < Hn; kc += 32){
            #pragma unroll
            for (int i = tid; i < 2048; i += 256){
                int m = i >> 5, kk = i & 31;
                float a = g_outhid[m*Hn + kc + kk];
                As2[kk][m] = pack2(a, a);
            }
            #pragma unroll
            for (int i4 = tid; i4 < 2048; i4 += 256){
                int row = i4 >> 3, k4 = i4 & 7;
                int v = vbase + row;
                float4 wv = (v < Vn) ? *(const float4*)&W[(size_t)v*Hn + kc + k4*4]
                                     : make_float4(0.f,0.f,0.f,0.f);
                Bs[k4*4+0][row] = wv.x; Bs[k4*4+1][row] = wv.y;
                Bs[k4*4+2][row] = wv.z; Bs[k4*4+3][row] = wv.w;
            }
            __syncthreads();
            #pragma unroll
            for (int kk = 0; kk < 32; kk++){
                ulonglong2 p0 = *(const ulonglong2*)&Bs[kk][n0];
                ulonglong2 p1 = *(const ulonglong2*)&Bs[kk][n0+4];
                #pragma unroll
                for (int i = 0; i < 8; i++){
                    unsigned long long a2 = As2[kk][m0 + i];
                    acc[i][0] = fma2_(a2, p0.x, acc[i][0]);
                    acc[i][1] = fma2_(a2, p0.y, acc[i][1]);
                    acc[i][2] = fma2_(a2, p1.x, acc[i][2]);
                    acc[i][3] = fma2_(a2, p1.y, acc[i][3]);
                }
            }
            __syncthreads();
        }
        float bvals[8];
        #pragma unroll
        for (int j = 0; j < 8; j++){
            int v = vbase + n0 + j;
            bvals[j] = (v < Vn) ? bias[v] : 0.0f;
        }
        #pragma unroll
        for (int i = 0; i < 8; i++){
            int m = m0 + i;
            float vals[8];
            unpack2(acc[i][0], vals[0], vals[1]);
            unpack2(acc[i][1], vals[2], vals[3]);
            unpack2(acc[i][2], vals[4], vals[5]);
            unpack2(acc[i][3], vals[6], vals[7]);
            float psum = 0.0f;
            #pragma unroll
            for (int j = 0; j < 8; j++){
                int v = vbase + n0 + j;
                if (v < Vn){
                    float ev = expf(vals[j] + bvals[j]);
                    g_elog[(size_t)m*Vn + v] = ev;
                    psum += ev;
                }
            }
            psum = warp_sum(psum);
            if (tx == 0) atomicAdd(&g_rowsum[m], psum);
        }
        __syncthreads();
    }
    grid_bar(&g_cnt2, &g_sense2, NBB);

    // ---------- phase F: final (float4, grid-stride) ----------
    for (int i4 = blockIdx.x * 256 + tid; i4 < (Bn*(Vn+Xn))/4; i4 += NBB*256){
        int i = i4 * 4;
        int b = i / (Vn+Xn);
        int v = i - b*(Vn+Xn);
        float4 r;
        if (v < Vn){
            float pg = out[OFF_PGEN + b];
            float inv = pg / g_rowsum[b];
            const float4 e4 = *(const float4*)&g_elog[(size_t)b*Vn + v];
            r.x = e4.x * inv; r.y = e4.y * inv; r.z = e4.z * inv; r.w = e4.w * inv;
        } else {
            r = *(const float4*)&extraz[b*Xn + (v - Vn)];
        }
        *(float4*)&out[OFF_FINAL + i] = r;
    }
    grid_bar(&g_cnt2, &g_sense2, NBB);

    // ---------- phase G: scatter (grid-stride) ----------
    for (int i = blockIdx.x * 256 + tid; i < Bn*Tn; i += NBB*256){
        int b = i / Tn;
        int ix = ebev[i];
        float pg = out[OFF_PGEN + b];
        float add = (1.0f - pg) * out[OFF_ATTN + i];
        atomicAdd(&out[OFF_FINAL + (size_t)b*(Vn+Xn) + ix], add);
    }
}

extern "C" void kernel_launch(void* const* d_in, const int* in_sizes, int n_in,
                              void* d_out, int out_size){
    const int*   y_t_1    = (const int*)  d_in[0];
    const float* h0       = (const float*)d_in[1];
    const float* c0       = (const float*)d_in[2];
    const float* eo       = (const float*)d_in[3];
    const float* ef       = (const float*)d_in[4];
    const float* stmt     = (const float*)d_in[5];
    const float* mask     = (const float*)d_in[6];
    const float* c_t_1    = (const float*)d_in[7];
    const float* extraz   = (const float*)d_in[8];
    const int*   ebev     = (const int*)  d_in[9];
    const float* coverage = (const float*)d_in[10];
    const float* embedding = (const float*)d_in[n_in-16];
    const float* Wxc  = (const float*)d_in[n_in-15];
    const float* bxc  = (const float*)d_in[n_in-14];
    const float* W_ih = (const float*)d_in[n_in-13];
    const float* W_hh = (const float*)d_in[n_in-12];
    const float* b_ih = (const float*)d_in[n_in-11];
    const float* b_hh = (const float*)d_in[n_in-10];
    const float* Wdp  = (const float*)d_in[n_in-9];
    const float* bdp  = (const float*)d_in[n_in-8];
    const float* Wv   = (const float*)d_in[n_in-7];
    const float* Wpg  = (const float*)d_in[n_in-6];
    const float* bpg  = (const float*)d_in[n_in-5];
    const float* Wo1  = (const float*)d_in[n_in-4];
    const float* bo1  = (const float*)d_in[n_in-3];
    const float* Wo2  = (const float*)d_in[n_in-2];
    const float* bo2  = (const float*)d_in[n_in-1];
    float* out = (float*)d_out;

    k_front<<<NBF, 1024>>>(y_t_1, c_t_1, embedding, Wxc, bxc, h0, c0,
                           W_ih, W_hh, b_ih, b_hh, Wdp, bdp, Wv, mask,
                           ef, eo, stmt, Wo1, bo1, Wpg, bpg, coverage, out);
    k_back<<<NBB, 256>>>(Wo2, bo2, extraz, ebev, out);
}